// round 7
// baseline (speedup 1.0000x reference)
#include <cuda_runtime.h>
#include <float.h>

#define BB 4096
#define NN 2048
#define NPAIR 3
#define ROW_THREADS 128          // 128 thr * 4 float4 = 512 float4 = one 2048-float row
#define NWORK (BB * NPAIR)       // 12288 worker CTAs
#define NBLOCKS (NWORK + 1)      // + 1 watcher CTA (bid 0)

// Per-(pair,row) weighted contributions + completion counter.
// Final sum is fixed-order -> deterministic regardless of completion order.
__device__ float g_partials[NPAIR * BB];
__device__ unsigned int g_count = 0;

__global__ __launch_bounds__(ROW_THREADS)
void wnrmse_kernel(const float* __restrict__ o1, const float* __restrict__ t1,
                   const float* __restrict__ o2, const float* __restrict__ t2,
                   const float* __restrict__ o3, const float* __restrict__ t3,
                   float* __restrict__ out) {
    const int tid = threadIdx.x;
    const int w = tid >> 5, l = tid & 31;

    if (blockIdx.x == 0) {
        // ---- Watcher CTA: resident from wave 1, naps until all workers done ----
        if (tid == 0) {
            unsigned int c;
            do {
                __nanosleep(200);
                asm volatile("ld.acquire.gpu.global.u32 %0, [%1];"
                             : "=r"(c) : "l"(&g_count) : "memory");
            } while (c != (unsigned)NWORK);
        }
        __syncthreads();   // all 128 threads wait for the release

        // Fixed-order reduction: 12288 floats = 3072 float4; 128 thr -> 24 each.
        const float4* __restrict__ p4 = reinterpret_cast<const float4*>(g_partials);
        float s = 0.0f;
        #pragma unroll
        for (int i = 0; i < 24; i++) {
            float4 v = p4[tid + i * ROW_THREADS];
            s += (v.x + v.y) + (v.z + v.w);
        }

        #pragma unroll
        for (int sh = 16; sh > 0; sh >>= 1)
            s += __shfl_xor_sync(0xFFFFFFFFu, s, sh);

        __shared__ float s_fin[4];
        if (l == 0) s_fin[w] = s;
        __syncthreads();
        if (tid == 0) {
            float a = (s_fin[0] + s_fin[1]) + (s_fin[2] + s_fin[3]);
            out[0] = a * (1.0f / BB);
            g_count = 0;   // reset for next graph replay (all increments already in)
        }
        return;
    }

    // ---- Worker CTA ----
    const int idx = blockIdx.x - 1;
    const int b = idx & (BB - 1);     // batch row
    const int p = idx >> 12;          // pair index (BB = 4096 = 2^12)

    const float* o = (p == 0) ? o1 : ((p == 1) ? o2 : o3);
    const float* t = (p == 0) ? t1 : ((p == 1) ? t2 : t3);

    const float4* __restrict__ o4 = reinterpret_cast<const float4*>(o + (size_t)b * NN);
    const float4* __restrict__ t4 = reinterpret_cast<const float4*>(t + (size_t)b * NN);

    // 8 front-batched LDG.128 per thread, all 128B-coalesced.
    float4 ov0 = o4[tid];
    float4 ov1 = o4[tid + ROW_THREADS];
    float4 ov2 = o4[tid + 2 * ROW_THREADS];
    float4 ov3 = o4[tid + 3 * ROW_THREADS];
    float4 tv0 = t4[tid];
    float4 tv1 = t4[tid + ROW_THREADS];
    float4 tv2 = t4[tid + 2 * ROW_THREADS];
    float4 tv3 = t4[tid + 3 * ROW_THREADS];

    float ssq = 0.0f, tmax = -FLT_MAX, tmin = FLT_MAX;
    {
        float d;
        d = ov0.x - tv0.x; ssq = fmaf(d, d, ssq); tmax = fmaxf(tmax, tv0.x); tmin = fminf(tmin, tv0.x);
        d = ov0.y - tv0.y; ssq = fmaf(d, d, ssq); tmax = fmaxf(tmax, tv0.y); tmin = fminf(tmin, tv0.y);
        d = ov0.z - tv0.z; ssq = fmaf(d, d, ssq); tmax = fmaxf(tmax, tv0.z); tmin = fminf(tmin, tv0.z);
        d = ov0.w - tv0.w; ssq = fmaf(d, d, ssq); tmax = fmaxf(tmax, tv0.w); tmin = fminf(tmin, tv0.w);
        d = ov1.x - tv1.x; ssq = fmaf(d, d, ssq); tmax = fmaxf(tmax, tv1.x); tmin = fminf(tmin, tv1.x);
        d = ov1.y - tv1.y; ssq = fmaf(d, d, ssq); tmax = fmaxf(tmax, tv1.y); tmin = fminf(tmin, tv1.y);
        d = ov1.z - tv1.z; ssq = fmaf(d, d, ssq); tmax = fmaxf(tmax, tv1.z); tmin = fminf(tmin, tv1.z);
        d = ov1.w - tv1.w; ssq = fmaf(d, d, ssq); tmax = fmaxf(tmax, tv1.w); tmin = fminf(tmin, tv1.w);
        d = ov2.x - tv2.x; ssq = fmaf(d, d, ssq); tmax = fmaxf(tmax, tv2.x); tmin = fminf(tmin, tv2.x);
        d = ov2.y - tv2.y; ssq = fmaf(d, d, ssq); tmax = fmaxf(tmax, tv2.y); tmin = fminf(tmin, tv2.y);
        d = ov2.z - tv2.z; ssq = fmaf(d, d, ssq); tmax = fmaxf(tmax, tv2.z); tmin = fminf(tmin, tv2.z);
        d = ov2.w - tv2.w; ssq = fmaf(d, d, ssq); tmax = fmaxf(tmax, tv2.w); tmin = fminf(tmin, tv2.w);
        d = ov3.x - tv3.x; ssq = fmaf(d, d, ssq); tmax = fmaxf(tmax, tv3.x); tmin = fminf(tmin, tv3.x);
        d = ov3.y - tv3.y; ssq = fmaf(d, d, ssq); tmax = fmaxf(tmax, tv3.y); tmin = fminf(tmin, tv3.y);
        d = ov3.z - tv3.z; ssq = fmaf(d, d, ssq); tmax = fmaxf(tmax, tv3.z); tmin = fminf(tmin, tv3.z);
        d = ov3.w - tv3.w; ssq = fmaf(d, d, ssq); tmax = fmaxf(tmax, tv3.w); tmin = fminf(tmin, tv3.w);
    }

    // Intra-warp reduce
    #pragma unroll
    for (int s = 16; s > 0; s >>= 1) {
        ssq  += __shfl_xor_sync(0xFFFFFFFFu, ssq,  s);
        tmax  = fmaxf(tmax, __shfl_xor_sync(0xFFFFFFFFu, tmax, s));
        tmin  = fminf(tmin, __shfl_xor_sync(0xFFFFFFFFu, tmin, s));
    }

    // Cross-warp reduce (4 warps)
    __shared__ float s_ssq[4], s_max[4], s_min[4];
    if (l == 0) { s_ssq[w] = ssq; s_max[w] = tmax; s_min[w] = tmin; }
    __syncthreads();

    if (tid == 0) {
        float a  = (s_ssq[0] + s_ssq[1]) + (s_ssq[2] + s_ssq[3]);
        float mx = fmaxf(fmaxf(s_max[0], s_max[1]), fmaxf(s_max[2], s_max[3]));
        float mn = fminf(fminf(s_min[0], s_min[1]), fminf(s_min[2], s_min[3]));
        const float wgt = (p == 0) ? 0.5f : 0.25f;
        g_partials[p * BB + b] = wgt * sqrtf(a * (1.0f / NN)) / (mx - mn);

        // Fire-and-forget release increment: no return value, no exit-path stall,
        // orders the partial store before the count at gpu scope.
        asm volatile("red.release.gpu.global.add.u32 [%0], %1;"
                     :: "l"(&g_count), "r"(1u) : "memory");
    }
}

extern "C" void kernel_launch(void* const* d_in, const int* in_sizes, int n_in,
                              void* d_out, int out_size) {
    const float* o1 = (const float*)d_in[0];
    const float* t1 = (const float*)d_in[1];
    const float* o2 = (const float*)d_in[2];
    const float* t2 = (const float*)d_in[3];
    const float* o3 = (const float*)d_in[4];
    const float* t3 = (const float*)d_in[5];
    float* out = (float*)d_out;

    wnrmse_kernel<<<NBLOCKS, ROW_THREADS>>>(o1, t1, o2, t2, o3, t3, out);
}